// round 15
// baseline (speedup 1.0000x reference)
#include <cuda_runtime.h>
#include <cuda_fp16.h>
#include <stdint.h>
#include <math.h>

#define BB 8
#define NN 2048
#define MM (BB * NN)
#define TUU 256
#define BN_SCALE_F 0.999500374687773f

static __device__ __constant__ const float kRads[3] = {0.1f, 0.3f, 0.7f};

// ---------------- scratch (device globals: allowed scratch path) ------------
__device__ float g_xm[BB * TUU];
__device__ float g_T[BB * 9];
__device__ __align__(16) float g_px[MM];
__device__ __align__(16) float g_py[MM];
__device__ __align__(16) float g_pz[MM];
__device__ __align__(16) float g_bufB[(size_t)MM * 512];   // f1 fp32 (residual src)
// fp16 activation ping-pong (single precision stream; weights carry the lo)
__device__ __align__(16) __half g_A0[(size_t)MM * 576];
__device__ __align__(16) __half g_A1[(size_t)MM * 576];
// transposed fp16 hi/lo weights, all 5 layers packed [Npad][K]
#define WTOT 1015808
__device__ __align__(16) __half g_Wh[WTOT];
__device__ __align__(16) __half g_Wl[WTOT];

// ---------------- baseline-ISA helpers (cp.async / ldmatrix / mma) ----------
__device__ __forceinline__ void cp16(uint32_t d, const void* s) {
    asm volatile("cp.async.cg.shared.global [%0], [%1], 16;" :: "r"(d), "l"(s));
}
#define LDMX4(R, addr) \
    asm volatile("ldmatrix.sync.aligned.m8n8.x4.shared.b16 {%0,%1,%2,%3}, [%4];" \
        : "=r"((R)[0]), "=r"((R)[1]), "=r"((R)[2]), "=r"((R)[3]) : "r"(addr))
#define MMA16(C, A, B) \
    asm volatile("mma.sync.aligned.m16n8k16.row.col.f32.f16.f16.f32 " \
        "{%0,%1,%2,%3}, {%4,%5,%6,%7}, {%8,%9}, {%0,%1,%2,%3};" \
        : "+f"((C)[0]), "+f"((C)[1]), "+f"((C)[2]), "+f"((C)[3]) \
        : "r"((A)[0]), "r"((A)[1]), "r"((A)[2]), "r"((A)[3]), \
          "r"((B)[0]), "r"((B)[1]))

// ---------------- init: zero xm + output ------------------------------------
__global__ void initk(float* out) {
    int i = blockIdx.x * blockDim.x + threadIdx.x;
    if (i < BB * TUU) g_xm[i] = 0.f;
    if (i < BB * 170) out[i] = 0.f;
}

// ---------------- T-Net stage 1 ---------------------------------------------
__global__ void tnet1(const float* __restrict__ points, const float* __restrict__ tw,
                      const float* __restrict__ tb, const float* __restrict__ tg1,
                      const float* __restrict__ tbt1) {
    int b = blockIdx.x, ch = blockIdx.y;
    __shared__ float sp[256 * 3];
    int base = (b * NN + ch * 256) * 3;
    for (int i = threadIdx.x; i < 768; i += 256) sp[i] = points[base + i];
    __syncthreads();
    int u = threadIdx.x;
    float w0 = tw[u], w1 = tw[256 + u], w2 = tw[512 + u], bz = tb[u];
    float ga = tg1[u] * BN_SCALE_F, be = tbt1[u];
    float m = 0.f;
    #pragma unroll 4
    for (int i = 0; i < 256; i++) {
        float x = sp[3 * i] * w0 + sp[3 * i + 1] * w1 + sp[3 * i + 2] * w2 + bz;
        x = fmaxf(x * ga + be, 0.f);
        m = fmaxf(m, x);
    }
    atomicMax((int*)&g_xm[b * 256 + u], __float_as_int(m));
}

// ---------------- T-Net stage 2 ---------------------------------------------
__global__ void tnet2(const float* __restrict__ td1w, const float* __restrict__ td1b,
                      const float* __restrict__ tg2, const float* __restrict__ tbt2,
                      const float* __restrict__ td2w, const float* __restrict__ td2b) {
    int b = blockIdx.x;
    __shared__ float xs[256], hs[256];
    int u = threadIdx.x;
    xs[u] = g_xm[b * 256 + u];
    __syncthreads();
    float acc = td1b[u];
    #pragma unroll 8
    for (int k = 0; k < 256; k++) acc += xs[k] * td1w[k * 256 + u];
    acc = acc * (tg2[u] * BN_SCALE_F) + tbt2[u];
    hs[u] = fmaxf(acc, 0.f);
    __syncthreads();
    if (u < 9) {
        float t = td2b[u];
        for (int k = 0; k < 256; k++) t += hs[k] * td2w[k * 9 + u];
        g_T[b * 9 + u] = t;
    }
}

// ---------------- apply T ----------------------------------------------------
__global__ void transformk(const float* __restrict__ points) {
    int gid = blockIdx.x * blockDim.x + threadIdx.x;
    if (gid >= MM) return;
    int b = gid >> 11;
    const float* T = &g_T[b * 9];
    float p0 = points[gid * 3], p1 = points[gid * 3 + 1], p2 = points[gid * 3 + 2];
    g_px[gid] = p0 * T[0] + p1 * T[3] + p2 * T[6];
    g_py[gid] = p0 * T[1] + p1 * T[4] + p2 * T[7];
    g_pz[gid] = p0 * T[2] + p1 * T[5] + p2 * T[8];
}

// ---------------- ball-query top-K select + gather (nested-radius) ----------
__global__ __launch_bounds__(256) void selectk(const float* __restrict__ noise) {
    __shared__ float spx[NN], spy[NN], spz[NN];          // 24 KB
    __shared__ unsigned long long cand[1024];            // 8 KB
    __shared__ float snr256[256];
    __shared__ int sel[3][64];
    __shared__ int warpsum[8];
    __shared__ int npA[3];
    __shared__ int sh_cnt, sh_M;
    int b = blockIdx.x >> 11, n = blockIdx.x & 2047;
    int tid = threadIdx.x, lane = tid & 31, w = tid >> 5;
    const float* nr = noise + (size_t)(b * NN + n) * NN;

    {
        const float4* gx = (const float4*)(g_px + b * NN);
        const float4* gy = (const float4*)(g_py + b * NN);
        const float4* gz = (const float4*)(g_pz + b * NN);
        #pragma unroll
        for (int i = tid; i < 512; i += 256) {
            ((float4*)spx)[i] = gx[i];
            ((float4*)spy)[i] = gy[i];
            ((float4*)spz)[i] = gz[i];
        }
    }
    if (tid == 0) sh_cnt = 0;
    snr256[tid] = nr[tid];
    __syncthreads();
    float qx = spx[n], qy = spy[n], qz = spz[n];
    float R2BIG = kRads[2] * kRads[2];

    for (int j = tid; j < NN; j += 256) {
        float nv = nr[j];
        float dx = qx - spx[j], dy = qy - spy[j], dz = qz - spz[j];
        float d2 = dx * dx + dy * dy + dz * dz;
        if (d2 <= R2BIG && nv > 0.f) {
            int pos = atomicAdd(&sh_cnt, 1);
            if (pos < 1024)
                cand[pos] = ((unsigned long long)__float_as_uint(nv) << 32) |
                            (unsigned int)(~j);
        }
    }
    __syncthreads();
    int cnt = sh_cnt;
    int C = cnt < 1024 ? cnt : 1024;
    int P = 64; while (P < C) P <<= 1;
    for (int i = C + tid; i < P; i += 256) cand[i] = 0ull;
    __syncthreads();
    for (int size = 2; size <= P; size <<= 1) {
        for (int stride = size >> 1; stride > 0; stride >>= 1) {
            for (int i = tid; i < P; i += 256) {
                int p = i ^ stride;
                if (p > i) {
                    bool desc = ((i & size) == 0);
                    unsigned long long a = cand[i], c = cand[p];
                    if (desc ? (a < c) : (a > c)) { cand[i] = c; cand[p] = a; }
                }
            }
            __syncthreads();
        }
    }
    {
        int np = cnt < 64 ? cnt : 64;
        if (tid < np) sel[2][tid] = (int)(~(unsigned int)(cand[tid] & 0xffffffffull));
        if (tid == 0) npA[2] = np;
    }
    for (int r = 0; r < 2; r++) {
        float r2 = kRads[r] * kRads[r];
        int base = tid * 4;
        bool fl[4]; int jj[4]; int cnt4 = 0;
        #pragma unroll
        for (int u = 0; u < 4; u++) {
            int i = base + u;
            bool f = false; int j = 0;
            if (i < C) {
                j = (int)(~(unsigned int)(cand[i] & 0xffffffffull));
                float dx = qx - spx[j], dy = qy - spy[j], dz = qz - spz[j];
                float d2 = dx * dx + dy * dy + dz * dz;
                f = (d2 <= r2);
            }
            fl[u] = f; jj[u] = j; cnt4 += f;
        }
        int scan = cnt4;
        #pragma unroll
        for (int o = 1; o < 32; o <<= 1) {
            int v = __shfl_up_sync(0xffffffffu, scan, o);
            if (lane >= o) scan += v;
        }
        if (lane == 31) warpsum[w] = scan;
        __syncthreads();
        if (tid == 0) {
            int run = 0;
            #pragma unroll
            for (int i = 0; i < 8; i++) { int t = warpsum[i]; warpsum[i] = run; run += t; }
            sh_M = run;
        }
        __syncthreads();
        int pos = warpsum[w] + scan - cnt4;
        #pragma unroll
        for (int u = 0; u < 4; u++)
            if (fl[u]) { if (pos < 64) sel[r][pos] = jj[u]; pos++; }
        if (tid == 0) { int M = sh_M; npA[r] = M < 64 ? M : 64; }
        __syncthreads();
    }
    for (int r = 0; r < 3; r++) {
        int np = npA[r];
        int need = 64 - np;
        if (need > 0) {
            float r2 = kRads[r] * kRads[r];
            int j = tid;
            float dx = qx - spx[j], dy = qy - spy[j], dz = qz - spz[j];
            float d2 = dx * dx + dy * dy + dz * dz;
            bool nq = !(d2 <= r2 && snr256[j] > 0.f);
            int scan = nq ? 1 : 0;
            #pragma unroll
            for (int o = 1; o < 32; o <<= 1) {
                int v = __shfl_up_sync(0xffffffffu, scan, o);
                if (lane >= o) scan += v;
            }
            if (lane == 31) warpsum[w] = scan;
            __syncthreads();
            if (tid == 0) {
                int run = 0;
                #pragma unroll
                for (int i = 0; i < 8; i++) { int t = warpsum[i]; warpsum[i] = run; run += t; }
            }
            __syncthreads();
            if (nq) {
                int pos = warpsum[w] + scan - 1;
                if (pos < need) sel[r][np + pos] = j;
            }
            __syncthreads();
        }
    }
    __syncthreads();
    // gather -> fp16 feats (buf 0), row stride 576
    __half* oh = &g_A0[(size_t)(b * NN + n) * 576];
    for (int t = tid; t < 576; t += 256) {
        int k = t / 9, rem = t - 9 * k, r = rem / 3, c = rem - 3 * r;
        int j = sel[r][k];
        float v = (c == 0) ? spx[j] : ((c == 1) ? spy[j] : spz[j]);
        oh[t] = __float2half(v);
    }
}

// ---------------- weight prep: transpose + fp16 hi/lo split (all layers) ----
__global__ void prepw_all(const float* __restrict__ c1w, const float* __restrict__ rw,
                          const float* __restrict__ b1w, const float* __restrict__ b2w,
                          const float* __restrict__ b3w) {
    int idx = blockIdx.x * 256 + threadIdx.x;
    if (idx >= WTOT) return;
    int off, K, N; const float* W;
    if (idx < 294912)      { off = 0;      K = 576; N = 512; W = c1w; }
    else if (idx < 557056) { off = 294912; K = 512; N = 512; W = rw; }
    else if (idx < 819200) { off = 557056; K = 512; N = 512; W = b1w; }
    else if (idx < 950272) { off = 819200; K = 512; N = 256; W = b2w; }
    else                   { off = 950272; K = 256; N = 170; W = b3w; }
    int local = idx - off;
    int n = local / K, k = local - n * K;
    float w = (n < N) ? W[(size_t)k * N + n] : 0.f;
    __half hi = __float2half(w);
    g_Wh[idx] = hi;
    g_Wl[idx] = __float2half(w - __half2float(hi));
}

// ---------------- smem chunk loader (3-stage cp.async pipeline) -------------
// Stage layout: A @0, Wh @10240, Wl @20480; rows padded to 80B. Stage=30720B.
__device__ __forceinline__ void load_chunk(
    uint32_t dstb, const __half* A, const __half* Wh, const __half* Wl,
    int m0, int n0, int K, int koff, int tid) {
    #pragma unroll
    for (int h = 0; h < 2; h++) {
        int gg = h * 256 + tid;
        int row = gg >> 2, seg = gg & 3;
        uint32_t doff = (uint32_t)(row * 80 + seg * 16);
        size_t aoff = (size_t)(m0 + row) * K + koff + seg * 8;
        size_t boff = (size_t)(n0 + row) * K + koff + seg * 8;
        cp16(dstb + doff,         A  + aoff);
        cp16(dstb + 10240 + doff, Wh + boff);
        cp16(dstb + 20480 + doff, Wl + boff);
    }
    asm volatile("cp.async.commit_group;" ::: "memory");
}

// ---------------- HMMA fp16x2 GEMM + fused epilogue -------------------------
// Block: 128x128, 8 warps (2x4), warp tile 64x32, mma.m16n8k16 f16->f32.
// 3-stage cp.async pipeline, ONE barrier per K-chunk:
//   wait(chunk kt) -> barrier (visibility + proves stage kt-1 fully consumed)
//   -> prefetch chunk kt+2 into stage (kt+2)%3 == (kt-1)%3 -> compute kt.
// 2-product split: A*Wh + A*Wl.
__global__ __launch_bounds__(256, 2) void gemm_mma(
    int srcA, int K, int woff,
    const float* __restrict__ bias, const float* __restrict__ gamma,
    const float* __restrict__ beta, int mode, int Nd, int ldo,
    float* __restrict__ outx) {
    extern __shared__ __align__(16) char sm_[];
    __shared__ float sB[128], sG[128], sE[128];
    __shared__ int colred[128];
    int tid = threadIdx.x, lane = tid & 31, wid = tid >> 5;
    int wm = wid >> 2, wn = wid & 3;
    int m0 = blockIdx.y * 128, n0 = blockIdx.x * 128;
    const __half* A = srcA ? g_A1 : g_A0;
    __half* D = srcA ? g_A0 : g_A1;
    const __half* Wh = g_Wh + woff;
    const __half* Wl = g_Wl + woff;

    if (tid < 128) {
        int c = n0 + tid;
        if (c < Nd) {
            sB[tid] = bias[c];
            sG[tid] = (mode == 1) ? 0.f : gamma[c] * BN_SCALE_F;
            sE[tid] = (mode == 1) ? 0.f : beta[c];
        } else { sB[tid] = sG[tid] = sE[tid] = 0.f; }
        colred[tid] = 0;
    }

    uint32_t sb = (uint32_t)__cvta_generic_to_shared(sm_);
    float acc[4][4][4];
    #pragma unroll
    for (int i = 0; i < 4; i++)
        #pragma unroll
        for (int j = 0; j < 4; j++)
            #pragma unroll
            for (int q = 0; q < 4; q++) acc[i][j][q] = 0.f;

    int nCh = K >> 5;
    load_chunk(sb, A, Wh, Wl, m0, n0, K, 0, tid);
    if (nCh > 1) load_chunk(sb + 30720, A, Wh, Wl, m0, n0, K, 32, tid);
    for (int kt = 0; kt < nCh; kt++) {
        if (kt + 1 < nCh) {
            asm volatile("cp.async.wait_group 1;" ::: "memory");
        } else {
            asm volatile("cp.async.wait_group 0;" ::: "memory");
        }
        __syncthreads();   // chunk kt visible; stage (kt-1)%3 fully consumed
        int kn = kt + 2;
        if (kn < nCh)
            load_chunk(sb + (uint32_t)((kn % 3) * 30720),
                       A, Wh, Wl, m0, n0, K, kn * 32, tid);
        uint32_t stb = sb + (uint32_t)((kt % 3) * 30720);
        #pragma unroll
        for (int sub = 0; sub < 2; sub++) {
            uint32_t a[4][4], bh[4][2], bl[4][2];
            #pragma unroll
            for (int n2 = 0; n2 < 2; n2++) {
                uint32_t r4[4];
                uint32_t bd = stb + 10240 +
                    (uint32_t)((wn * 32 + n2 * 16 + ((lane >> 4) & 1) * 8 + (lane & 7)) * 80) +
                    (uint32_t)(((lane >> 3) & 1) * 16 + sub * 32);
                LDMX4(r4, bd);
                bh[n2 * 2][0] = r4[0]; bh[n2 * 2][1] = r4[1];
                bh[n2 * 2 + 1][0] = r4[2]; bh[n2 * 2 + 1][1] = r4[3];
                LDMX4(r4, bd + 10240);
                bl[n2 * 2][0] = r4[0]; bl[n2 * 2][1] = r4[1];
                bl[n2 * 2 + 1][0] = r4[2]; bl[n2 * 2 + 1][1] = r4[3];
            }
            #pragma unroll
            for (int mt = 0; mt < 4; mt++) {
                uint32_t ad = stb +
                    (uint32_t)((wm * 64 + mt * 16 + (lane & 15)) * 80) +
                    (uint32_t)(((lane >> 4) & 1) * 16 + sub * 32);
                LDMX4(a[mt], ad);
            }
            #pragma unroll
            for (int mt = 0; mt < 4; mt++)
                #pragma unroll
                for (int nt = 0; nt < 4; nt++) MMA16(acc[mt][nt], a[mt], bh[nt]);
            #pragma unroll
            for (int mt = 0; mt < 4; mt++)
                #pragma unroll
                for (int nt = 0; nt < 4; nt++) MMA16(acc[mt][nt], a[mt], bl[nt]);
        }
    }

    // ---- epilogue ----
    int g = lane >> 2, tg = lane & 3;
    #pragma unroll
    for (int mt = 0; mt < 4; mt++) {
        int r0 = m0 + wm * 64 + mt * 16 + g;
        #pragma unroll
        for (int nt = 0; nt < 4; nt++) {
            int cl = wn * 32 + nt * 8 + tg * 2;
            int c0 = n0 + cl;
            float v00 = acc[mt][nt][0], v01 = acc[mt][nt][1];
            float v10 = acc[mt][nt][2], v11 = acc[mt][nt][3];
            if (mode == 3) {
                float y00 = fmaxf(fmaf(v00 + sB[cl], sG[cl], sE[cl]), 0.f);
                float y10 = fmaxf(fmaf(v10 + sB[cl], sG[cl], sE[cl]), 0.f);
                float y01 = fmaxf(fmaf(v01 + sB[cl + 1], sG[cl + 1], sE[cl + 1]), 0.f);
                float y11 = fmaxf(fmaf(v11 + sB[cl + 1], sG[cl + 1], sE[cl + 1]), 0.f);
                if (c0 < Nd)
                    atomicMax(&colred[cl], __float_as_int(fmaxf(y00, y10)));
                if (c0 + 1 < Nd)
                    atomicMax(&colred[cl + 1], __float_as_int(fmaxf(y01, y11)));
            } else if (mode == 1) {
                float2 f0 = *reinterpret_cast<const float2*>(&g_bufB[(size_t)r0 * 512 + c0]);
                float2 f1 = *reinterpret_cast<const float2*>(&g_bufB[(size_t)(r0 + 8) * 512 + c0]);
                float y00 = f0.x + v00 + sB[cl], y01 = f0.y + v01 + sB[cl + 1];
                float y10 = f1.x + v10 + sB[cl], y11 = f1.y + v11 + sB[cl + 1];
                *reinterpret_cast<__half2*>(D + (size_t)r0 * ldo + c0) =
                    __floats2half2_rn(y00, y01);
                *reinterpret_cast<__half2*>(D + (size_t)(r0 + 8) * ldo + c0) =
                    __floats2half2_rn(y10, y11);
            } else {
                float y00 = fmaxf(fmaf(v00 + sB[cl], sG[cl], sE[cl]), 0.f);
                float y01 = fmaxf(fmaf(v01 + sB[cl + 1], sG[cl + 1], sE[cl + 1]), 0.f);
                float y10 = fmaxf(fmaf(v10 + sB[cl], sG[cl], sE[cl]), 0.f);
                float y11 = fmaxf(fmaf(v11 + sB[cl + 1], sG[cl + 1], sE[cl + 1]), 0.f);
                *reinterpret_cast<__half2*>(D + (size_t)r0 * ldo + c0) =
                    __floats2half2_rn(y00, y01);
                *reinterpret_cast<__half2*>(D + (size_t)(r0 + 8) * ldo + c0) =
                    __floats2half2_rn(y10, y11);
                if (mode == 0) {
                    *reinterpret_cast<float2*>(&g_bufB[(size_t)r0 * 512 + c0]) =
                        make_float2(y00, y01);
                    *reinterpret_cast<float2*>(&g_bufB[(size_t)(r0 + 8) * 512 + c0]) =
                        make_float2(y10, y11);
                }
            }
        }
    }
    if (mode == 3) {
        __syncthreads();
        if (tid < 128) {
            int c = n0 + tid;
            if (c < Nd) {
                int b = m0 >> 11;
                atomicMax((int*)&outx[b * Nd + c], colred[tid]);
            }
        }
    }
}

// ---------------- launch ----------------------------------------------------
extern "C" void kernel_launch(void* const* d_in, const int* in_sizes, int n_in,
                              void* d_out, int out_size) {
    const float* points = (const float*)d_in[0];
    const float* noise  = (const float*)d_in[1];
    const float* tw     = (const float*)d_in[2];
    const float* tb     = (const float*)d_in[3];
    const float* tg1    = (const float*)d_in[4];
    const float* tbt1   = (const float*)d_in[5];
    const float* td1w   = (const float*)d_in[6];
    const float* td1b   = (const float*)d_in[7];
    const float* tg2    = (const float*)d_in[8];
    const float* tbt2   = (const float*)d_in[9];
    const float* td2w   = (const float*)d_in[10];
    const float* td2b   = (const float*)d_in[11];
    const float* c1w    = (const float*)d_in[12];
    const float* c1b    = (const float*)d_in[13];
    const float* g1     = (const float*)d_in[14];
    const float* be1    = (const float*)d_in[15];
    const float* rw     = (const float*)d_in[16];
    const float* rb     = (const float*)d_in[17];
    const float* b1w    = (const float*)d_in[18];
    const float* b1b    = (const float*)d_in[19];
    const float* b1g    = (const float*)d_in[20];
    const float* b1be   = (const float*)d_in[21];
    const float* b2w    = (const float*)d_in[22];
    const float* b2b    = (const float*)d_in[23];
    const float* b2g    = (const float*)d_in[24];
    const float* b2be   = (const float*)d_in[25];
    const float* b3w    = (const float*)d_in[26];
    const float* b3b    = (const float*)d_in[27];
    const float* b3g    = (const float*)d_in[28];
    const float* b3be   = (const float*)d_in[29];
    float* out = (float*)d_out;

    initk<<<8, 256>>>(out);
    tnet1<<<dim3(8, 8), 256>>>(points, tw, tb, tg1, tbt1);
    tnet2<<<8, 256>>>(td1w, td1b, tg2, tbt2, td2w, td2b);
    transformk<<<64, 256>>>(points);
    prepw_all<<<(WTOT + 255) / 256, 256>>>(c1w, rw, b1w, b2w, b3w);
    selectk<<<MM, 256>>>(noise);

    const int dyn = 92160;  // 3 stages x 30720B
    cudaFuncSetAttribute(gemm_mma, cudaFuncAttributeMaxDynamicSharedMemorySize, dyn);
    // L1: A0 (K=576) @ c1w -> relu/bn -> A1 + f1 fp32
    gemm_mma<<<dim3(4, 128), 256, dyn>>>(0, 576, 0,      c1b, g1,  be1,  0, 512, 512, nullptr);
    // L2: A1 @ rw, residual f1 + . + rb -> A0
    gemm_mma<<<dim3(4, 128), 256, dyn>>>(1, 512, 294912, rb,  rb,  rb,   1, 512, 512, nullptr);
    // L3: A0 @ b1w -> relu/bn -> A1
    gemm_mma<<<dim3(4, 128), 256, dyn>>>(0, 512, 557056, b1b, b1g, b1be, 2, 512, 512, nullptr);
    // L4: A1 @ b2w -> relu/bn -> A0 (ldo 256)
    gemm_mma<<<dim3(2, 128), 256, dyn>>>(1, 512, 819200, b2b, b2g, b2be, 2, 256, 256, nullptr);
    // L5: A0 (K=256) @ b3w(pad 256) -> relu/bn -> col-max -> out[8,170]
    gemm_mma<<<dim3(2, 128), 256, dyn>>>(0, 256, 950272, b3b, b3g, b3be, 3, 170, 0,   out);
}

// round 16
// speedup vs baseline: 1.1615x; 1.1615x over previous
#include <cuda_runtime.h>
#include <cuda_fp16.h>
#include <stdint.h>
#include <math.h>

#define BB 8
#define NN 2048
#define MM (BB * NN)
#define TUU 256
#define BN_SCALE_F 0.999500374687773f

static __device__ __constant__ const float kRads[3] = {0.1f, 0.3f, 0.7f};

// ---------------- scratch (device globals: allowed scratch path) ------------
__device__ float g_xm[BB * TUU];
__device__ float g_T[BB * 9];
__device__ __align__(16) float g_px[MM];
__device__ __align__(16) float g_py[MM];
__device__ __align__(16) float g_pz[MM];
__device__ __align__(16) float g_bufB[(size_t)MM * 512];   // f1 fp32 (residual src)
// fp16 activation ping-pong
__device__ __align__(16) __half g_A0[(size_t)MM * 576];
__device__ __align__(16) __half g_A1[(size_t)MM * 576];
// transposed fp16 weights, all 5 layers packed [Npad][K]
#define WTOT 1015808
__device__ __align__(16) __half g_Wh[WTOT];

// ---------------- baseline-ISA helpers (cp.async / ldmatrix / mma) ----------
__device__ __forceinline__ void cp16(uint32_t d, const void* s) {
    asm volatile("cp.async.cg.shared.global [%0], [%1], 16;" :: "r"(d), "l"(s));
}
#define LDMX4(R, addr) \
    asm volatile("ldmatrix.sync.aligned.m8n8.x4.shared.b16 {%0,%1,%2,%3}, [%4];" \
        : "=r"((R)[0]), "=r"((R)[1]), "=r"((R)[2]), "=r"((R)[3]) : "r"(addr))
#define MMA16(C, A, B) \
    asm volatile("mma.sync.aligned.m16n8k16.row.col.f32.f16.f16.f32 " \
        "{%0,%1,%2,%3}, {%4,%5,%6,%7}, {%8,%9}, {%0,%1,%2,%3};" \
        : "+f"((C)[0]), "+f"((C)[1]), "+f"((C)[2]), "+f"((C)[3]) \
        : "r"((A)[0]), "r"((A)[1]), "r"((A)[2]), "r"((A)[3]), \
          "r"((B)[0]), "r"((B)[1]))

// ---------------- init: zero xm + output ------------------------------------
__global__ void initk(float* out) {
    int i = blockIdx.x * blockDim.x + threadIdx.x;
    if (i < BB * TUU) g_xm[i] = 0.f;
    if (i < BB * 170) out[i] = 0.f;
}

// ---------------- T-Net stage 1 ---------------------------------------------
__global__ void tnet1(const float* __restrict__ points, const float* __restrict__ tw,
                      const float* __restrict__ tb, const float* __restrict__ tg1,
                      const float* __restrict__ tbt1) {
    int b = blockIdx.x, ch = blockIdx.y;
    __shared__ float sp[256 * 3];
    int base = (b * NN + ch * 256) * 3;
    for (int i = threadIdx.x; i < 768; i += 256) sp[i] = points[base + i];
    __syncthreads();
    int u = threadIdx.x;
    float w0 = tw[u], w1 = tw[256 + u], w2 = tw[512 + u], bz = tb[u];
    float ga = tg1[u] * BN_SCALE_F, be = tbt1[u];
    float m = 0.f;
    #pragma unroll 4
    for (int i = 0; i < 256; i++) {
        float x = sp[3 * i] * w0 + sp[3 * i + 1] * w1 + sp[3 * i + 2] * w2 + bz;
        x = fmaxf(x * ga + be, 0.f);
        m = fmaxf(m, x);
    }
    atomicMax((int*)&g_xm[b * 256 + u], __float_as_int(m));
}

// ---------------- T-Net stage 2 ---------------------------------------------
__global__ void tnet2(const float* __restrict__ td1w, const float* __restrict__ td1b,
                      const float* __restrict__ tg2, const float* __restrict__ tbt2,
                      const float* __restrict__ td2w, const float* __restrict__ td2b) {
    int b = blockIdx.x;
    __shared__ float xs[256], hs[256];
    int u = threadIdx.x;
    xs[u] = g_xm[b * 256 + u];
    __syncthreads();
    float acc = td1b[u];
    #pragma unroll 8
    for (int k = 0; k < 256; k++) acc += xs[k] * td1w[k * 256 + u];
    acc = acc * (tg2[u] * BN_SCALE_F) + tbt2[u];
    hs[u] = fmaxf(acc, 0.f);
    __syncthreads();
    if (u < 9) {
        float t = td2b[u];
        for (int k = 0; k < 256; k++) t += hs[k] * td2w[k * 9 + u];
        g_T[b * 9 + u] = t;
    }
}

// ---------------- apply T ----------------------------------------------------
__global__ void transformk(const float* __restrict__ points) {
    int gid = blockIdx.x * blockDim.x + threadIdx.x;
    if (gid >= MM) return;
    int b = gid >> 11;
    const float* T = &g_T[b * 9];
    float p0 = points[gid * 3], p1 = points[gid * 3 + 1], p2 = points[gid * 3 + 2];
    g_px[gid] = p0 * T[0] + p1 * T[3] + p2 * T[6];
    g_py[gid] = p0 * T[1] + p1 * T[4] + p2 * T[7];
    g_pz[gid] = p0 * T[2] + p1 * T[5] + p2 * T[8];
}

// ---------------- ball-query top-K select + gather (nested-radius) ----------
__global__ __launch_bounds__(256) void selectk(const float* __restrict__ noise) {
    __shared__ float spx[NN], spy[NN], spz[NN];          // 24 KB
    __shared__ unsigned long long cand[1024];            // 8 KB
    __shared__ float snr256[256];
    __shared__ int sel[3][64];
    __shared__ int warpsum[8];
    __shared__ int npA[3];
    __shared__ int sh_cnt, sh_M;
    int b = blockIdx.x >> 11, n = blockIdx.x & 2047;
    int tid = threadIdx.x, lane = tid & 31, w = tid >> 5;
    const float* nr = noise + (size_t)(b * NN + n) * NN;

    {
        const float4* gx = (const float4*)(g_px + b * NN);
        const float4* gy = (const float4*)(g_py + b * NN);
        const float4* gz = (const float4*)(g_pz + b * NN);
        #pragma unroll
        for (int i = tid; i < 512; i += 256) {
            ((float4*)spx)[i] = gx[i];
            ((float4*)spy)[i] = gy[i];
            ((float4*)spz)[i] = gz[i];
        }
    }
    if (tid == 0) sh_cnt = 0;
    snr256[tid] = nr[tid];
    __syncthreads();
    float qx = spx[n], qy = spy[n], qz = spz[n];
    float R2BIG = kRads[2] * kRads[2];

    for (int j = tid; j < NN; j += 256) {
        float nv = nr[j];
        float dx = qx - spx[j], dy = qy - spy[j], dz = qz - spz[j];
        float d2 = dx * dx + dy * dy + dz * dz;
        if (d2 <= R2BIG && nv > 0.f) {
            int pos = atomicAdd(&sh_cnt, 1);
            if (pos < 1024)
                cand[pos] = ((unsigned long long)__float_as_uint(nv) << 32) |
                            (unsigned int)(~j);
        }
    }
    __syncthreads();
    int cnt = sh_cnt;
    int C = cnt < 1024 ? cnt : 1024;
    int P = 64; while (P < C) P <<= 1;
    for (int i = C + tid; i < P; i += 256) cand[i] = 0ull;
    __syncthreads();
    for (int size = 2; size <= P; size <<= 1) {
        for (int stride = size >> 1; stride > 0; stride >>= 1) {
            for (int i = tid; i < P; i += 256) {
                int p = i ^ stride;
                if (p > i) {
                    bool desc = ((i & size) == 0);
                    unsigned long long a = cand[i], c = cand[p];
                    if (desc ? (a < c) : (a > c)) { cand[i] = c; cand[p] = a; }
                }
            }
            __syncthreads();
        }
    }
    {
        int np = cnt < 64 ? cnt : 64;
        if (tid < np) sel[2][tid] = (int)(~(unsigned int)(cand[tid] & 0xffffffffull));
        if (tid == 0) npA[2] = np;
    }
    for (int r = 0; r < 2; r++) {
        float r2 = kRads[r] * kRads[r];
        int base = tid * 4;
        bool fl[4]; int jj[4]; int cnt4 = 0;
        #pragma unroll
        for (int u = 0; u < 4; u++) {
            int i = base + u;
            bool f = false; int j = 0;
            if (i < C) {
                j = (int)(~(unsigned int)(cand[i] & 0xffffffffull));
                float dx = qx - spx[j], dy = qy - spy[j], dz = qz - spz[j];
                float d2 = dx * dx + dy * dy + dz * dz;
                f = (d2 <= r2);
            }
            fl[u] = f; jj[u] = j; cnt4 += f;
        }
        int scan = cnt4;
        #pragma unroll
        for (int o = 1; o < 32; o <<= 1) {
            int v = __shfl_up_sync(0xffffffffu, scan, o);
            if (lane >= o) scan += v;
        }
        if (lane == 31) warpsum[w] = scan;
        __syncthreads();
        if (tid == 0) {
            int run = 0;
            #pragma unroll
            for (int i = 0; i < 8; i++) { int t = warpsum[i]; warpsum[i] = run; run += t; }
            sh_M = run;
        }
        __syncthreads();
        int pos = warpsum[w] + scan - cnt4;
        #pragma unroll
        for (int u = 0; u < 4; u++)
            if (fl[u]) { if (pos < 64) sel[r][pos] = jj[u]; pos++; }
        if (tid == 0) { int M = sh_M; npA[r] = M < 64 ? M : 64; }
        __syncthreads();
    }
    for (int r = 0; r < 3; r++) {
        int np = npA[r];
        int need = 64 - np;
        if (need > 0) {
            float r2 = kRads[r] * kRads[r];
            int j = tid;
            float dx = qx - spx[j], dy = qy - spy[j], dz = qz - spz[j];
            float d2 = dx * dx + dy * dy + dz * dz;
            bool nq = !(d2 <= r2 && snr256[j] > 0.f);
            int scan = nq ? 1 : 0;
            #pragma unroll
            for (int o = 1; o < 32; o <<= 1) {
                int v = __shfl_up_sync(0xffffffffu, scan, o);
                if (lane >= o) scan += v;
            }
            if (lane == 31) warpsum[w] = scan;
            __syncthreads();
            if (tid == 0) {
                int run = 0;
                #pragma unroll
                for (int i = 0; i < 8; i++) { int t = warpsum[i]; warpsum[i] = run; run += t; }
            }
            __syncthreads();
            if (nq) {
                int pos = warpsum[w] + scan - 1;
                if (pos < need) sel[r][np + pos] = j;
            }
            __syncthreads();
        }
    }
    __syncthreads();
    // gather -> fp16 feats (buf 0), row stride 576
    __half* oh = &g_A0[(size_t)(b * NN + n) * 576];
    for (int t = tid; t < 576; t += 256) {
        int k = t / 9, rem = t - 9 * k, r = rem / 3, c = rem - 3 * r;
        int j = sel[r][k];
        float v = (c == 0) ? spx[j] : ((c == 1) ? spy[j] : spz[j]);
        oh[t] = __float2half(v);
    }
}

// ---------------- weight prep: transpose + fp16 convert (all layers) --------
__global__ void prepw_all(const float* __restrict__ c1w, const float* __restrict__ rw,
                          const float* __restrict__ b1w, const float* __restrict__ b2w,
                          const float* __restrict__ b3w) {
    int idx = blockIdx.x * 256 + threadIdx.x;
    if (idx >= WTOT) return;
    int off, K, N; const float* W;
    if (idx < 294912)      { off = 0;      K = 576; N = 512; W = c1w; }
    else if (idx < 557056) { off = 294912; K = 512; N = 512; W = rw; }
    else if (idx < 819200) { off = 557056; K = 512; N = 512; W = b1w; }
    else if (idx < 950272) { off = 819200; K = 512; N = 256; W = b2w; }
    else                   { off = 950272; K = 256; N = 170; W = b3w; }
    int local = idx - off;
    int n = local / K, k = local - n * K;
    float w = (n < N) ? W[(size_t)k * N + n] : 0.f;
    g_Wh[idx] = __float2half(w);
}

// ---------------- smem chunk loader (3-stage cp.async pipeline) -------------
// Stage layout: A @0, Wh @10240; rows padded to 80B. Stage=20480B.
__device__ __forceinline__ void load_chunk(
    uint32_t dstb, const __half* A, const __half* Wh,
    int m0, int n0, int K, int koff, int tid) {
    #pragma unroll
    for (int h = 0; h < 2; h++) {
        int gg = h * 256 + tid;
        int row = gg >> 2, seg = gg & 3;
        uint32_t doff = (uint32_t)(row * 80 + seg * 16);
        size_t aoff = (size_t)(m0 + row) * K + koff + seg * 8;
        size_t boff = (size_t)(n0 + row) * K + koff + seg * 8;
        cp16(dstb + doff,         A  + aoff);
        cp16(dstb + 10240 + doff, Wh + boff);
    }
    asm volatile("cp.async.commit_group;" ::: "memory");
}

// ---------------- HMMA fp16 GEMM + fused epilogue ---------------------------
// Block: 128x128, 8 warps (2x4), warp tile 64x32, mma.m16n8k16 f16->f32.
// Single-product fp16 (fp32 accum); weight-lo dropped (error budget verified).
__global__ __launch_bounds__(256, 2) void gemm_mma(
    int srcA, int K, int woff,
    const float* __restrict__ bias, const float* __restrict__ gamma,
    const float* __restrict__ beta, int mode, int Nd, int ldo,
    float* __restrict__ outx) {
    extern __shared__ __align__(16) char sm_[];
    __shared__ float sB[128], sG[128], sE[128];
    __shared__ int colred[128];
    int tid = threadIdx.x, lane = tid & 31, wid = tid >> 5;
    int wm = wid >> 2, wn = wid & 3;
    int m0 = blockIdx.y * 128, n0 = blockIdx.x * 128;
    const __half* A = srcA ? g_A1 : g_A0;
    __half* D = srcA ? g_A0 : g_A1;
    const __half* Wh = g_Wh + woff;

    if (tid < 128) {
        int c = n0 + tid;
        if (c < Nd) {
            sB[tid] = bias[c];
            sG[tid] = (mode == 1) ? 0.f : gamma[c] * BN_SCALE_F;
            sE[tid] = (mode == 1) ? 0.f : beta[c];
        } else { sB[tid] = sG[tid] = sE[tid] = 0.f; }
        colred[tid] = 0;
    }

    uint32_t sb = (uint32_t)__cvta_generic_to_shared(sm_);
    float acc[4][4][4];
    #pragma unroll
    for (int i = 0; i < 4; i++)
        #pragma unroll
        for (int j = 0; j < 4; j++)
            #pragma unroll
            for (int q = 0; q < 4; q++) acc[i][j][q] = 0.f;

    int nCh = K >> 5;
    load_chunk(sb, A, Wh, m0, n0, K, 0, tid);
    if (nCh > 1) load_chunk(sb + 20480, A, Wh, m0, n0, K, 32, tid);
    for (int kt = 0; kt < nCh; kt++) {
        if (kt + 1 < nCh) {
            asm volatile("cp.async.wait_group 1;" ::: "memory");
        } else {
            asm volatile("cp.async.wait_group 0;" ::: "memory");
        }
        __syncthreads();   // chunk kt visible; stage (kt-1)%3 fully consumed
        int kn = kt + 2;
        if (kn < nCh)
            load_chunk(sb + (uint32_t)((kn % 3) * 20480),
                       A, Wh, m0, n0, K, kn * 32, tid);
        uint32_t stb = sb + (uint32_t)((kt % 3) * 20480);
        #pragma unroll
        for (int sub = 0; sub < 2; sub++) {
            uint32_t a[4][4], bh[4][2];
            #pragma unroll
            for (int n2 = 0; n2 < 2; n2++) {
                uint32_t r4[4];
                uint32_t bd = stb + 10240 +
                    (uint32_t)((wn * 32 + n2 * 16 + ((lane >> 4) & 1) * 8 + (lane & 7)) * 80) +
                    (uint32_t)(((lane >> 3) & 1) * 16 + sub * 32);
                LDMX4(r4, bd);
                bh[n2 * 2][0] = r4[0]; bh[n2 * 2][1] = r4[1];
                bh[n2 * 2 + 1][0] = r4[2]; bh[n2 * 2 + 1][1] = r4[3];
            }
            #pragma unroll
            for (int mt = 0; mt < 4; mt++) {
                uint32_t ad = stb +
                    (uint32_t)((wm * 64 + mt * 16 + (lane & 15)) * 80) +
                    (uint32_t)(((lane >> 4) & 1) * 16 + sub * 32);
                LDMX4(a[mt], ad);
            }
            #pragma unroll
            for (int mt = 0; mt < 4; mt++)
                #pragma unroll
                for (int nt = 0; nt < 4; nt++) MMA16(acc[mt][nt], a[mt], bh[nt]);
        }
    }

    // ---- epilogue ----
    int g = lane >> 2, tg = lane & 3;
    #pragma unroll
    for (int mt = 0; mt < 4; mt++) {
        int r0 = m0 + wm * 64 + mt * 16 + g;
        #pragma unroll
        for (int nt = 0; nt < 4; nt++) {
            int cl = wn * 32 + nt * 8 + tg * 2;
            int c0 = n0 + cl;
            float v00 = acc[mt][nt][0], v01 = acc[mt][nt][1];
            float v10 = acc[mt][nt][2], v11 = acc[mt][nt][3];
            if (mode == 3) {
                float y00 = fmaxf(fmaf(v00 + sB[cl], sG[cl], sE[cl]), 0.f);
                float y10 = fmaxf(fmaf(v10 + sB[cl], sG[cl], sE[cl]), 0.f);
                float y01 = fmaxf(fmaf(v01 + sB[cl + 1], sG[cl + 1], sE[cl + 1]), 0.f);
                float y11 = fmaxf(fmaf(v11 + sB[cl + 1], sG[cl + 1], sE[cl + 1]), 0.f);
                if (c0 < Nd)
                    atomicMax(&colred[cl], __float_as_int(fmaxf(y00, y10)));
                if (c0 + 1 < Nd)
                    atomicMax(&colred[cl + 1], __float_as_int(fmaxf(y01, y11)));
            } else if (mode == 1) {
                float2 f0 = *reinterpret_cast<const float2*>(&g_bufB[(size_t)r0 * 512 + c0]);
                float2 f1 = *reinterpret_cast<const float2*>(&g_bufB[(size_t)(r0 + 8) * 512 + c0]);
                float y00 = f0.x + v00 + sB[cl], y01 = f0.y + v01 + sB[cl + 1];
                float y10 = f1.x + v10 + sB[cl], y11 = f1.y + v11 + sB[cl + 1];
                *reinterpret_cast<__half2*>(D + (size_t)r0 * ldo + c0) =
                    __floats2half2_rn(y00, y01);
                *reinterpret_cast<__half2*>(D + (size_t)(r0 + 8) * ldo + c0) =
                    __floats2half2_rn(y10, y11);
            } else {
                float y00 = fmaxf(fmaf(v00 + sB[cl], sG[cl], sE[cl]), 0.f);
                float y01 = fmaxf(fmaf(v01 + sB[cl + 1], sG[cl + 1], sE[cl + 1]), 0.f);
                float y10 = fmaxf(fmaf(v10 + sB[cl], sG[cl], sE[cl]), 0.f);
                float y11 = fmaxf(fmaf(v11 + sB[cl + 1], sG[cl + 1], sE[cl + 1]), 0.f);
                *reinterpret_cast<__half2*>(D + (size_t)r0 * ldo + c0) =
                    __floats2half2_rn(y00, y01);
                *reinterpret_cast<__half2*>(D + (size_t)(r0 + 8) * ldo + c0) =
                    __floats2half2_rn(y10, y11);
                if (mode == 0) {
                    *reinterpret_cast<float2*>(&g_bufB[(size_t)r0 * 512 + c0]) =
                        make_float2(y00, y01);
                    *reinterpret_cast<float2*>(&g_bufB[(size_t)(r0 + 8) * 512 + c0]) =
                        make_float2(y10, y11);
                }
            }
        }
    }
    if (mode == 3) {
        __syncthreads();
        if (tid < 128) {
            int c = n0 + tid;
            if (c < Nd) {
                int b = m0 >> 11;
                atomicMax((int*)&outx[b * Nd + c], colred[tid]);
            }
        }
    }
}

// ---------------- launch ----------------------------------------------------
extern "C" void kernel_launch(void* const* d_in, const int* in_sizes, int n_in,
                              void* d_out, int out_size) {
    const float* points = (const float*)d_in[0];
    const float* noise  = (const float*)d_in[1];
    const float* tw     = (const float*)d_in[2];
    const float* tb     = (const float*)d_in[3];
    const float* tg1    = (const float*)d_in[4];
    const float* tbt1   = (const float*)d_in[5];
    const float* td1w   = (const float*)d_in[6];
    const float* td1b   = (const float*)d_in[7];
    const float* tg2    = (const float*)d_in[8];
    const float* tbt2   = (const float*)d_in[9];
    const float* td2w   = (const float*)d_in[10];
    const float* td2b   = (const float*)d_in[11];
    const float* c1w    = (const float*)d_in[12];
    const float* c1b    = (const float*)d_in[13];
    const float* g1     = (const float*)d_in[14];
    const float* be1    = (const float*)d_in[15];
    const float* rw     = (const float*)d_in[16];
    const float* rb     = (const float*)d_in[17];
    const float* b1w    = (const float*)d_in[18];
    const float* b1b    = (const float*)d_in[19];
    const float* b1g    = (const float*)d_in[20];
    const float* b1be   = (const float*)d_in[21];
    const float* b2w    = (const float*)d_in[22];
    const float* b2b    = (const float*)d_in[23];
    const float* b2g    = (const float*)d_in[24];
    const float* b2be   = (const float*)d_in[25];
    const float* b3w    = (const float*)d_in[26];
    const float* b3b    = (const float*)d_in[27];
    const float* b3g    = (const float*)d_in[28];
    const float* b3be   = (const float*)d_in[29];
    float* out = (float*)d_out;

    initk<<<8, 256>>>(out);
    tnet1<<<dim3(8, 8), 256>>>(points, tw, tb, tg1, tbt1);
    tnet2<<<8, 256>>>(td1w, td1b, tg2, tbt2, td2w, td2b);
    transformk<<<64, 256>>>(points);
    prepw_all<<<(WTOT + 255) / 256, 256>>>(c1w, rw, b1w, b2w, b3w);
    selectk<<<MM, 256>>>(noise);

    const int dyn = 61440;  // 3 stages x 20480B
    cudaFuncSetAttribute(gemm_mma, cudaFuncAttributeMaxDynamicSharedMemorySize, dyn);
    // L1: A0 (K=576) @ c1w -> relu/bn -> A1 + f1 fp32
    gemm_mma<<<dim3(4, 128), 256, dyn>>>(0, 576, 0,      c1b, g1,  be1,  0, 512, 512, nullptr);
    // L2: A1 @ rw, residual f1 + . + rb -> A0
    gemm_mma<<<dim3(4, 128), 256, dyn>>>(1, 512, 294912, rb,  rb,  rb,   1, 512, 512, nullptr);
    // L3: A0 @ b1w -> relu/bn -> A1
    gemm_mma<<<dim3(4, 128), 256, dyn>>>(0, 512, 557056, b1b, b1g, b1be, 2, 512, 512, nullptr);
    // L4: A1 @ b2w -> relu/bn -> A0 (ldo 256)
    gemm_mma<<<dim3(2, 128), 256, dyn>>>(1, 512, 819200, b2b, b2g, b2be, 2, 256, 256, nullptr);
    // L5: A0 (K=256) @ b3w(pad 256) -> relu/bn -> col-max -> out[8,170]
    gemm_mma<<<dim3(2, 128), 256, dyn>>>(0, 256, 950272, b3b, b3g, b3be, 3, 170, 0,   out);
}